// round 5
// baseline (speedup 1.0000x reference)
#include <cuda_runtime.h>
#include <cuda_fp16.h>
#include <cstdint>

#define NT    16384
#define DIM   2048
#define NE    64
#define TT    64             // tokens per CTA
#define KCH   64             // k per smem chunk
#define NCHK  (DIM / KCH)    // 32
#define LSTR  66
#define GAP_THRESH 1e-4f

// smem fp16 planes, 64 rows x 128B, XOR-16B-chunk swizzle
#define XH 0
#define XM 8192
#define WH 16384
#define WM 24576
#define SMEM_TOTAL 32768     // logits (64*66*4=16896) reuse stage area

__device__ __forceinline__ uint32_t smem_u32(const void* p) {
    uint32_t a;
    asm("{ .reg .u64 t; cvta.to.shared.u64 t, %1; cvt.u32.u64 %0, t; }" : "=r"(a) : "l"(p));
    return a;
}

__device__ __forceinline__ void split2(float2 v, uint32_t& h, uint32_t& m) {
    __half2 hh = __float22half2_rn(v);
    float2 hf = __half22float2(hh);
    __half2 mm = __floats2half2_rn(v.x - hf.x, v.y - hf.y);
    h = *reinterpret_cast<uint32_t*>(&hh);
    m = *reinterpret_cast<uint32_t*>(&mm);
}

__device__ __forceinline__ void ldm4(uint32_t addr, uint32_t& r0, uint32_t& r1,
                                     uint32_t& r2, uint32_t& r3) {
    asm volatile("ldmatrix.sync.aligned.m8n8.x4.shared.b16 {%0,%1,%2,%3}, [%4];"
                 : "=r"(r0), "=r"(r1), "=r"(r2), "=r"(r3) : "r"(addr));
}

__device__ __forceinline__ void mma16816(float* c, const uint32_t* a,
                                         uint32_t b0, uint32_t b1) {
    asm volatile("mma.sync.aligned.m16n8k16.row.col.f32.f16.f16.f32 "
                 "{%0,%1,%2,%3}, {%4,%5,%6,%7}, {%8,%9}, {%0,%1,%2,%3};"
                 : "+f"(c[0]), "+f"(c[1]), "+f"(c[2]), "+f"(c[3])
                 : "r"(a[0]), "r"(a[1]), "r"(a[2]), "r"(a[3]), "r"(b0), "r"(b1));
}

__global__ __launch_bounds__(256, 2)
void router_hmma(const float* __restrict__ x, const float* __restrict__ w,
                 float* __restrict__ out)
{
    extern __shared__ __align__(16) char smem[];
    const uint32_t sb = smem_u32(smem);

    __shared__ int   s_cnt;
    __shared__ int   s_list[TT];
    __shared__ float s_part[4][64];
    __shared__ float s_lg[66];

    const int tid  = threadIdx.x;
    const int lane = tid & 31;
    const int wp   = tid >> 5;       // 0..7
    const int tg   = wp & 3;         // token group (x16)
    const int eh   = wp >> 2;        // expert half (x32)
    const int tok0 = blockIdx.x * TT;

    if (tid == 0) s_cnt = 0;

    // ---- conversion thread mapping: token/expert row = tid>>2, 16 k per thread ----
    const int crow = tid >> 2;
    const int ckq  = (tid & 3) * 16;
    const float* xg = x + (size_t)(tok0 + crow) * DIM + ckq;
    const float* wg = w + (size_t)crow * DIM + ckq;
    // two uint4 stores per plane: logical chunks cc0, cc0+1, XOR-swizzled by row
    const int cc0 = (tid & 3) * 2;
    uint32_t st0 = (uint32_t)(crow * 128 + (((cc0 + 0) ^ (crow & 7)) << 4));
    uint32_t st1 = (uint32_t)(crow * 128 + (((cc0 + 1) ^ (crow & 7)) << 4));

    // ---- ldmatrix lane addressing ----
    const int l7 = lane & 7, gA = (lane >> 3) & 1, gB = lane >> 4;
    const uint32_t aRow = (uint32_t)((tg * 16 + l7 + gA * 8) * 128);
    const uint32_t bRow0 = (uint32_t)((eh * 32 + 0  + l7 + gB * 8) * 128);
    const uint32_t bRow1 = (uint32_t)((eh * 32 + 16 + l7 + gB * 8) * 128);

    float acc[4][4];
#pragma unroll
    for (int j = 0; j < 4; j++)
#pragma unroll
        for (int q = 0; q < 4; q++) acc[j][q] = 0.0f;

    float4 rx[4], rw[4];
    auto loadc = [&](int ch) {
        const int kb = ch * KCH;
#pragma unroll
        for (int i = 0; i < 4; i++)
            rx[i] = *reinterpret_cast<const float4*>(xg + kb + i * 4);
#pragma unroll
        for (int i = 0; i < 4; i++)
            rw[i] = *reinterpret_cast<const float4*>(wg + kb + i * 4);
    };
    loadc(0);

    for (int ch = 0; ch < NCHK; ch++) {
        __syncthreads();   // previous chunk's compute done, stage free
        {
            uint32_t h[8], m[8];
#pragma unroll
            for (int i = 0; i < 4; i++) {
                split2(make_float2(rx[i].x, rx[i].y), h[2 * i],     m[2 * i]);
                split2(make_float2(rx[i].z, rx[i].w), h[2 * i + 1], m[2 * i + 1]);
            }
            *reinterpret_cast<uint4*>(smem + XH + st0) = make_uint4(h[0], h[1], h[2], h[3]);
            *reinterpret_cast<uint4*>(smem + XH + st1) = make_uint4(h[4], h[5], h[6], h[7]);
            *reinterpret_cast<uint4*>(smem + XM + st0) = make_uint4(m[0], m[1], m[2], m[3]);
            *reinterpret_cast<uint4*>(smem + XM + st1) = make_uint4(m[4], m[5], m[6], m[7]);
#pragma unroll
            for (int i = 0; i < 4; i++) {
                split2(make_float2(rw[i].x * 256.0f, rw[i].y * 256.0f), h[2 * i],     m[2 * i]);
                split2(make_float2(rw[i].z * 256.0f, rw[i].w * 256.0f), h[2 * i + 1], m[2 * i + 1]);
            }
            *reinterpret_cast<uint4*>(smem + WH + st0) = make_uint4(h[0], h[1], h[2], h[3]);
            *reinterpret_cast<uint4*>(smem + WH + st1) = make_uint4(h[4], h[5], h[6], h[7]);
            *reinterpret_cast<uint4*>(smem + WM + st0) = make_uint4(m[0], m[1], m[2], m[3]);
            *reinterpret_cast<uint4*>(smem + WM + st1) = make_uint4(m[4], m[5], m[6], m[7]);
        }
        __syncthreads();
        if (ch + 1 < NCHK) loadc(ch + 1);   // overlap next LDG with compute

#pragma unroll
        for (int s = 0; s < 4; s++) {
            const uint32_t csA = (uint32_t)(((2 * s + gB) ^ l7) << 4);
            const uint32_t csB = (uint32_t)(((2 * s + gA) ^ l7) << 4);
            uint32_t ah[4], am[4], bh[8], bm[8];
            ldm4(sb + XH + aRow + csA, ah[0], ah[1], ah[2], ah[3]);
            ldm4(sb + XM + aRow + csA, am[0], am[1], am[2], am[3]);
            ldm4(sb + WH + bRow0 + csB, bh[0], bh[1], bh[2], bh[3]);
            ldm4(sb + WH + bRow1 + csB, bh[4], bh[5], bh[6], bh[7]);
#pragma unroll
            for (int j = 0; j < 4; j++) mma16816(acc[j], ah, bh[2 * j], bh[2 * j + 1]);
#pragma unroll
            for (int j = 0; j < 4; j++) mma16816(acc[j], am, bh[2 * j], bh[2 * j + 1]);
            ldm4(sb + WM + bRow0 + csB, bm[0], bm[1], bm[2], bm[3]);
            ldm4(sb + WM + bRow1 + csB, bm[4], bm[5], bm[6], bm[7]);
#pragma unroll
            for (int j = 0; j < 4; j++) mma16816(acc[j], ah, bm[2 * j], bm[2 * j + 1]);
        }
    }

    // ---- logits -> smem (undo x256 w scale) ----
    __syncthreads();
    float* ls = reinterpret_cast<float*>(smem);
    {
        const int qrow = lane >> 2, qk = (lane & 3) * 2;
        const int r0 = tg * 16 + qrow, r1 = r0 + 8;
        const int e00 = eh * 32 + qk;
#pragma unroll
        for (int j = 0; j < 4; j++) {
            int e = e00 + 8 * j;
            *reinterpret_cast<float2*>(ls + r0 * LSTR + e) =
                make_float2(acc[j][0] * 0.00390625f, acc[j][1] * 0.00390625f);
            *reinterpret_cast<float2*>(ls + r1 * LSTR + e) =
                make_float2(acc[j][2] * 0.00390625f, acc[j][3] * 0.00390625f);
        }
    }
    __syncthreads();

    float* outp = out;
    float* outi = out + (size_t)NT * 8;
    float* outa = out + (size_t)NT * 16;

    const int tbase = wp * 8;
#pragma unroll 1
    for (int tt = 0; tt < 8; tt++) {
        const int tok = tbase + tt;
        float2 v = *reinterpret_cast<const float2*>(ls + tok * LSTR + 2 * lane);

        float m = fmaxf(v.x, v.y);
#pragma unroll
        for (int o = 16; o > 0; o >>= 1)
            m = fmaxf(m, __shfl_xor_sync(0xffffffffu, m, o));

        float e0 = expf(v.x - m);
        float e1 = expf(v.y - m);
        float ssum = e0 + e1;
#pragma unroll
        for (int o = 16; o > 0; o >>= 1)
            ssum += __shfl_xor_sync(0xffffffffu, ssum, o);

        float inv = 1.0f / ssum;
        float p0 = e0 * inv, p1 = e1 * inv;

        const int gtok = tok0 + tok;
        *reinterpret_cast<float2*>(outa + (size_t)gtok * 64 + 2 * lane)
            = make_float2(p0, p1);

        // top-9 on logits, track min adjacent gap
        float c0 = v.x, c1 = v.y;
        int i0 = 2 * lane, i1 = 2 * lane + 1;
        float tv = 0.0f, tsum = 0.0f, prevv = 0.0f, mingap = 1e30f;
        int ti = 0;
#pragma unroll
        for (int r = 0; r < 9; r++) {
            float bv; int bi;
            if (c0 > c1 || (c0 == c1 && i0 < i1)) { bv = c0; bi = i0; }
            else                                  { bv = c1; bi = i1; }
#pragma unroll
            for (int o = 16; o > 0; o >>= 1) {
                float ov = __shfl_xor_sync(0xffffffffu, bv, o);
                int   oi = __shfl_xor_sync(0xffffffffu, bi, o);
                if (ov > bv || (ov == bv && oi < bi)) { bv = ov; bi = oi; }
            }
            if (r > 0) mingap = fminf(mingap, prevv - bv);
            prevv = bv;
            if (r < 8) {
                float bp = expf(bv - m) * inv;
                tsum += bp;
                if (lane == r) { tv = bp; ti = bi; }
                if (bi == i0)      c0 = -1e30f;
                else if (bi == i1) c1 = -1e30f;
            }
        }
        if (lane < 8) {
            outp[(size_t)gtok * 8 + lane] = tv / (tsum + 1e-9f);
            outi[(size_t)gtok * 8 + lane] = (float)ti;
        }
        if (lane == 0 && mingap < GAP_THRESH) {
            int pos = atomicAdd(&s_cnt, 1);
            s_list[pos] = gtok;
        }
    }

    // ---- inline exact fp32 fixup for this CTA's flagged tokens ----
    __syncthreads();
    const int nfix = s_cnt;
    for (int i = 0; i < nfix; i++) {
        const int tok = s_list[i];
        const int e = tid & 63, kp = tid >> 6;
        const float* xr = x + (size_t)tok * DIM + kp * 512;
        const float* wr = w + (size_t)e * DIM + kp * 512;
        float s = 0.0f;
#pragma unroll 4
        for (int k = 0; k < 512; k += 4) {
            float4 xv = *reinterpret_cast<const float4*>(xr + k);
            float4 wv = *reinterpret_cast<const float4*>(wr + k);
            s = fmaf(xv.x, wv.x, s);
            s = fmaf(xv.y, wv.y, s);
            s = fmaf(xv.z, wv.z, s);
            s = fmaf(xv.w, wv.w, s);
        }
        s_part[kp][e] = s;
        __syncthreads();
        if (tid < 64)
            s_lg[tid] = (s_part[0][tid] + s_part[1][tid]) + (s_part[2][tid] + s_part[3][tid]);
        __syncthreads();

        if (tid < 32) {
            float2 v = make_float2(s_lg[2 * lane], s_lg[2 * lane + 1]);

            float m = fmaxf(v.x, v.y);
#pragma unroll
            for (int o = 16; o > 0; o >>= 1)
                m = fmaxf(m, __shfl_xor_sync(0xffffffffu, m, o));

            float e0 = expf(v.x - m);
            float e1 = expf(v.y - m);
            float ssum = e0 + e1;
#pragma unroll
            for (int o = 16; o > 0; o >>= 1)
                ssum += __shfl_xor_sync(0xffffffffu, ssum, o);

            float inv = 1.0f / ssum;
            float p0 = e0 * inv, p1 = e1 * inv;

            *reinterpret_cast<float2*>(outa + (size_t)tok * 64 + 2 * lane)
                = make_float2(p0, p1);

            float c0 = p0, c1 = p1;
            int i0 = 2 * lane, i1 = 2 * lane + 1;
            float tv = 0.0f, tsum = 0.0f;
            int ti = 0;
#pragma unroll
            for (int r = 0; r < 8; r++) {
                float bv; int bi;
                if (c0 > c1 || (c0 == c1 && i0 < i1)) { bv = c0; bi = i0; }
                else                                  { bv = c1; bi = i1; }
#pragma unroll
                for (int o = 16; o > 0; o >>= 1) {
                    float ov = __shfl_xor_sync(0xffffffffu, bv, o);
                    int   oi = __shfl_xor_sync(0xffffffffu, bi, o);
                    if (ov > bv || (ov == bv && oi < bi)) { bv = ov; bi = oi; }
                }
                tsum += bv;
                if (lane == r) { tv = bv; ti = bi; }
                if (bi == i0)      c0 = -1.0f;
                else if (bi == i1) c1 = -1.0f;
            }
            if (lane < 8) {
                outp[(size_t)tok * 8 + lane] = tv / (tsum + 1e-9f);
                outi[(size_t)tok * 8 + lane] = (float)ti;
            }
        }
        __syncthreads();
    }
}

extern "C" void kernel_launch(void* const* d_in, const int* in_sizes, int n_in,
                              void* d_out, int out_size)
{
    (void)in_sizes; (void)n_in; (void)out_size;
    const float* x = (const float*)d_in[0];
    const float* w = (const float*)d_in[1];
    cudaFuncSetAttribute(router_hmma, cudaFuncAttributeMaxDynamicSharedMemorySize,
                         SMEM_TOTAL);
    router_hmma<<<NT / TT, 256, SMEM_TOTAL>>>(x, w, (float*)d_out);
}

// round 6
// speedup vs baseline: 1.0411x; 1.0411x over previous
#include <cuda_runtime.h>
#include <cuda_fp16.h>
#include <cstdint>

#define NT    16384
#define DIM   2048
#define NE    64
#define TT    64             // tokens per CTA
#define KCH   128            // k per w chunk
#define NCHK  (DIM / KCH)    // 16
#define NKS   (DIM / 16)     // 128 k16 steps
#define LSTR  66
#define GAP_THRESH 1e-4f

#define PLANE_BYTES 16384    // 64 rows x 256B
#define BUF_BYTES   32768    // h + m planes
#define SMEM_TOTAL  65536    // 2 stages

__device__ __align__(16) __half g_wh[NE * DIM];
__device__ __align__(16) __half g_wm[NE * DIM];

__device__ __forceinline__ uint32_t smem_u32(const void* p) {
    uint32_t a;
    asm("{ .reg .u64 t; cvta.to.shared.u64 t, %1; cvt.u32.u64 %0, t; }" : "=r"(a) : "l"(p));
    return a;
}

__device__ __forceinline__ void split2(float2 v, uint32_t& h, uint32_t& m) {
    __half2 hh = __float22half2_rn(v);
    float2 hf = __half22float2(hh);
    __half2 mm = __floats2half2_rn(v.x - hf.x, v.y - hf.y);
    h = *reinterpret_cast<uint32_t*>(&hh);
    m = *reinterpret_cast<uint32_t*>(&mm);
}

__device__ __forceinline__ void ldm4(uint32_t addr, uint32_t& r0, uint32_t& r1,
                                     uint32_t& r2, uint32_t& r3) {
    asm volatile("ldmatrix.sync.aligned.m8n8.x4.shared.b16 {%0,%1,%2,%3}, [%4];"
                 : "=r"(r0), "=r"(r1), "=r"(r2), "=r"(r3) : "r"(addr));
}

__device__ __forceinline__ void mma16816(float* c, const uint32_t* a,
                                         uint32_t b0, uint32_t b1) {
    asm volatile("mma.sync.aligned.m16n8k16.row.col.f32.f16.f16.f32 "
                 "{%0,%1,%2,%3}, {%4,%5,%6,%7}, {%8,%9}, {%0,%1,%2,%3};"
                 : "+f"(c[0]), "+f"(c[1]), "+f"(c[2]), "+f"(c[3])
                 : "r"(a[0]), "r"(a[1]), "r"(a[2]), "r"(a[3]), "r"(b0), "r"(b1));
}

#define CP16(sa, ga) \
    asm volatile("cp.async.ca.shared.global [%0], [%1], 16;" :: "r"(sa), "l"(ga))
#define CP_COMMIT() asm volatile("cp.async.commit_group;" ::: "memory")
#define CP_WAIT(n)  asm volatile("cp.async.wait_group %0;" :: "n"(n) : "memory")

// ---- prep: w -> fp16 h/m planes (scaled by 256), runs once per replay ----
__global__ __launch_bounds__(256) void prep_w(const float* __restrict__ w) {
    const int base = (blockIdx.x * 256 + threadIdx.x) * 8;   // 64 blocks
    float4 a = *reinterpret_cast<const float4*>(w + base);
    float4 b = *reinterpret_cast<const float4*>(w + base + 4);
    uint32_t h[4], m[4];
    split2(make_float2(a.x * 256.0f, a.y * 256.0f), h[0], m[0]);
    split2(make_float2(a.z * 256.0f, a.w * 256.0f), h[1], m[1]);
    split2(make_float2(b.x * 256.0f, b.y * 256.0f), h[2], m[2]);
    split2(make_float2(b.z * 256.0f, b.w * 256.0f), h[3], m[3]);
    *reinterpret_cast<uint4*>(g_wh + base) = make_uint4(h[0], h[1], h[2], h[3]);
    *reinterpret_cast<uint4*>(g_wm + base) = make_uint4(m[0], m[1], m[2], m[3]);
}

// ---- main ----
__global__ __launch_bounds__(256, 2)
void router_hmma(const float* __restrict__ x, const float* __restrict__ w,
                 float* __restrict__ out)
{
    extern __shared__ __align__(1024) char smem[];
    const uint32_t sb = smem_u32(smem);

    __shared__ int   s_cnt;
    __shared__ int   s_list[TT];
    __shared__ float s_part[4][64];
    __shared__ float s_lg[66];

    const int tid  = threadIdx.x;
    const int lane = tid & 31;
    const int wp   = tid >> 5;       // 0..7
    const int tg   = wp & 3;         // token group (x16)
    const int eh   = wp >> 2;        // expert half (x32)
    const int tok0 = blockIdx.x * TT;

    if (tid == 0) s_cnt = 0;

    // B ldmatrix lane addressing (proven mapping from rounds 3-5)
    const int l7 = lane & 7;
    const int gk = (lane >> 3) & 1;                 // k8 half select
    const int rA = eh * 32 + ((lane >> 4) << 3) + l7;   // n-tiles 0,1
    const int rB = rA + 16;                              // n-tiles 2,3
    const uint32_t rAoff = (uint32_t)(rA * 256), rAs = (uint32_t)(rA & 7);
    const uint32_t rBoff = (uint32_t)(rB * 256), rBs = (uint32_t)(rB & 7);

    // A fragment gmem addressing (round-4 proven)
    const int qrow = lane >> 2, qk = (lane & 3) * 2;
    const float* xa = x + (size_t)(tok0 + tg * 16 + qrow) * DIM + qk;

    float acc[4][4];
#pragma unroll
    for (int j = 0; j < 4; j++)
#pragma unroll
        for (int q = 0; q < 4; q++) acc[j][q] = 0.0f;

    float2 pa[2][4];
    auto loadA = [&](int g, int s) {
        const float* p = xa + 16 * g;
        pa[s][0] = *reinterpret_cast<const float2*>(p);
        pa[s][1] = *reinterpret_cast<const float2*>(p + 8);
        pa[s][2] = *reinterpret_cast<const float2*>(p + 8 * DIM);
        pa[s][3] = *reinterpret_cast<const float2*>(p + 8 * DIM + 8);
    };

    // cp.async w-chunk stage: 1024 uint4 per plane, 4 per thread per plane
    auto issueW = [&](int ch, int buf) {
#pragma unroll
        for (int it = 0; it < 4; it++) {
            int i = tid + 256 * it;
            int row = i >> 4, c = i & 15;
            uint32_t sa = sb + (uint32_t)(buf * BUF_BYTES + row * 256 +
                                          ((c ^ (row & 7)) << 4));
            const __half* gh = g_wh + (size_t)row * DIM + ch * KCH + c * 8;
            const __half* gm = g_wm + (size_t)row * DIM + ch * KCH + c * 8;
            CP16(sa, gh);
            CP16(sa + PLANE_BYTES, gm);
        }
    };

    loadA(0, 0);
    loadA(1, 1);
    issueW(0, 0);
    CP_COMMIT();

    for (int ch = 0; ch < NCHK; ch++) {
        if (ch + 1 < NCHK) { issueW(ch + 1, (ch + 1) & 1); CP_COMMIT(); CP_WAIT(1); }
        else               { CP_WAIT(0); }
        __syncthreads();

        const uint32_t bufb = sb + (uint32_t)((ch & 1) * BUF_BYTES);
#pragma unroll
        for (int ks = 0; ks < 8; ks++) {
            const int g = ch * 8 + ks;
            const int s = g & 1;

            uint32_t ah[4], am[4];
            split2(pa[s][0], ah[0], am[0]);
            split2(pa[s][2], ah[1], am[1]);
            split2(pa[s][1], ah[2], am[2]);
            split2(pa[s][3], ah[3], am[3]);
            if (g + 2 < NKS) loadA(g + 2, s);

            const uint32_t c = (uint32_t)(2 * ks + gk);
            const uint32_t offA = rAoff + ((c ^ rAs) << 4);
            const uint32_t offB = rBoff + ((c ^ rBs) << 4);
            uint32_t bh[8], bm[8];
            ldm4(bufb + offA, bh[0], bh[1], bh[2], bh[3]);
            ldm4(bufb + offB, bh[4], bh[5], bh[6], bh[7]);
#pragma unroll
            for (int j = 0; j < 4; j++) mma16816(acc[j], ah, bh[2 * j], bh[2 * j + 1]);
#pragma unroll
            for (int j = 0; j < 4; j++) mma16816(acc[j], am, bh[2 * j], bh[2 * j + 1]);
            ldm4(bufb + PLANE_BYTES + offA, bm[0], bm[1], bm[2], bm[3]);
            ldm4(bufb + PLANE_BYTES + offB, bm[4], bm[5], bm[6], bm[7]);
#pragma unroll
            for (int j = 0; j < 4; j++) mma16816(acc[j], ah, bm[2 * j], bm[2 * j + 1]);
        }
        __syncthreads();
    }

    // ---- logits -> smem (undo x256 w scale) ----
    float* ls = reinterpret_cast<float*>(smem);
    {
        const int r0 = tg * 16 + qrow, r1 = r0 + 8;
        const int e00 = eh * 32 + qk;
#pragma unroll
        for (int j = 0; j < 4; j++) {
            int e = e00 + 8 * j;
            *reinterpret_cast<float2*>(ls + r0 * LSTR + e) =
                make_float2(acc[j][0] * 0.00390625f, acc[j][1] * 0.00390625f);
            *reinterpret_cast<float2*>(ls + r1 * LSTR + e) =
                make_float2(acc[j][2] * 0.00390625f, acc[j][3] * 0.00390625f);
        }
    }
    __syncthreads();

    float* outp = out;
    float* outi = out + (size_t)NT * 8;
    float* outa = out + (size_t)NT * 16;

    const int tbase = wp * 8;
#pragma unroll 1
    for (int tt = 0; tt < 8; tt++) {
        const int tok = tbase + tt;
        float2 v = *reinterpret_cast<const float2*>(ls + tok * LSTR + 2 * lane);

        float m = fmaxf(v.x, v.y);
#pragma unroll
        for (int o = 16; o > 0; o >>= 1)
            m = fmaxf(m, __shfl_xor_sync(0xffffffffu, m, o));

        float e0 = expf(v.x - m);
        float e1 = expf(v.y - m);
        float ssum = e0 + e1;
#pragma unroll
        for (int o = 16; o > 0; o >>= 1)
            ssum += __shfl_xor_sync(0xffffffffu, ssum, o);

        float inv = 1.0f / ssum;
        float p0 = e0 * inv, p1 = e1 * inv;

        const int gtok = tok0 + tok;
        *reinterpret_cast<float2*>(outa + (size_t)gtok * 64 + 2 * lane)
            = make_float2(p0, p1);

        // top-9 on logits, track min adjacent gap
        float c0 = v.x, c1 = v.y;
        int i0 = 2 * lane, i1 = 2 * lane + 1;
        float tv = 0.0f, tsum = 0.0f, prevv = 0.0f, mingap = 1e30f;
        int ti = 0;
#pragma unroll
        for (int r = 0; r < 9; r++) {
            float bv; int bi;
            if (c0 > c1 || (c0 == c1 && i0 < i1)) { bv = c0; bi = i0; }
            else                                  { bv = c1; bi = i1; }
#pragma unroll
            for (int o = 16; o > 0; o >>= 1) {
                float ov = __shfl_xor_sync(0xffffffffu, bv, o);
                int   oi = __shfl_xor_sync(0xffffffffu, bi, o);
                if (ov > bv || (ov == bv && oi < bi)) { bv = ov; bi = oi; }
            }
            if (r > 0) mingap = fminf(mingap, prevv - bv);
            prevv = bv;
            if (r < 8) {
                float bp = expf(bv - m) * inv;
                tsum += bp;
                if (lane == r) { tv = bp; ti = bi; }
                if (bi == i0)      c0 = -1e30f;
                else if (bi == i1) c1 = -1e30f;
            }
        }
        if (lane < 8) {
            outp[(size_t)gtok * 8 + lane] = tv / (tsum + 1e-9f);
            outi[(size_t)gtok * 8 + lane] = (float)ti;
        }
        if (lane == 0 && mingap < GAP_THRESH) {
            int pos = atomicAdd(&s_cnt, 1);
            s_list[pos] = gtok;
        }
    }

    // ---- inline exact fp32 fixup for flagged tokens ----
    __syncthreads();
    const int nfix = s_cnt;
    for (int i = 0; i < nfix; i++) {
        const int tok = s_list[i];
        const int e = tid & 63, kp = tid >> 6;
        const float* xr = x + (size_t)tok * DIM + kp * 512;
        const float* wr = w + (size_t)e * DIM + kp * 512;
        float s = 0.0f;
#pragma unroll 4
        for (int k = 0; k < 512; k += 4) {
            float4 xv = *reinterpret_cast<const float4*>(xr + k);
            float4 wv = *reinterpret_cast<const float4*>(wr + k);
            s = fmaf(xv.x, wv.x, s);
            s = fmaf(xv.y, wv.y, s);
            s = fmaf(xv.z, wv.z, s);
            s = fmaf(xv.w, wv.w, s);
        }
        s_part[kp][e] = s;
        __syncthreads();
        if (tid < 64)
            s_lg[tid] = (s_part[0][tid] + s_part[1][tid]) + (s_part[2][tid] + s_part[3][tid]);
        __syncthreads();

        if (tid < 32) {
            float2 v = make_float2(s_lg[2 * lane], s_lg[2 * lane + 1]);

            float m = fmaxf(v.x, v.y);
#pragma unroll
            for (int o = 16; o > 0; o >>= 1)
                m = fmaxf(m, __shfl_xor_sync(0xffffffffu, m, o));

            float e0 = expf(v.x - m);
            float e1 = expf(v.y - m);
            float ssum = e0 + e1;
#pragma unroll
            for (int o = 16; o > 0; o >>= 1)
                ssum += __shfl_xor_sync(0xffffffffu, ssum, o);

            float inv = 1.0f / ssum;
            float p0 = e0 * inv, p1 = e1 * inv;

            *reinterpret_cast<float2*>(outa + (size_t)tok * 64 + 2 * lane)
                = make_float2(p0, p1);

            float c0 = p0, c1 = p1;
            int i0 = 2 * lane, i1 = 2 * lane + 1;
            float tv = 0.0f, tsum = 0.0f;
            int ti = 0;
#pragma unroll
            for (int r = 0; r < 8; r++) {
                float bv; int bi;
                if (c0 > c1 || (c0 == c1 && i0 < i1)) { bv = c0; bi = i0; }
                else                                  { bv = c1; bi = i1; }
#pragma unroll
                for (int o = 16; o > 0; o >>= 1) {
                    float ov = __shfl_xor_sync(0xffffffffu, bv, o);
                    int   oi = __shfl_xor_sync(0xffffffffu, bi, o);
                    if (ov > bv || (ov == bv && oi < bi)) { bv = ov; bi = oi; }
                }
                tsum += bv;
                if (lane == r) { tv = bv; ti = bi; }
                if (bi == i0)      c0 = -1.0f;
                else if (bi == i1) c1 = -1.0f;
            }
            if (lane < 8) {
                outp[(size_t)tok * 8 + lane] = tv / (tsum + 1e-9f);
                outi[(size_t)tok * 8 + lane] = (float)ti;
            }
        }
        __syncthreads();
    }
}

extern "C" void kernel_launch(void* const* d_in, const int* in_sizes, int n_in,
                              void* d_out, int out_size)
{
    (void)in_sizes; (void)n_in; (void)out_size;
    const float* x = (const float*)d_in[0];
    const float* w = (const float*)d_in[1];
    cudaFuncSetAttribute(router_hmma, cudaFuncAttributeMaxDynamicSharedMemorySize,
                         SMEM_TOTAL);
    prep_w<<<NE * DIM / (256 * 8), 256>>>(w);
    router_hmma<<<NT / TT, 256, SMEM_TOTAL>>>(x, w, (float*)d_out);
}